// round 1
// baseline (speedup 1.0000x reference)
#include <cuda_runtime.h>
#include <math.h>

// Problem constants
#define T_   2048
#define HID_ 4096
#define NH_  16
#define D_   256
#define QKV_N_ (3 * HID_)   // 12288
#define EPS_ 1e-6f

// ---------------------------------------------------------------------------
// Scratch (device globals — no allocation allowed)
// ---------------------------------------------------------------------------
__device__ float g_qkv [T_ * QKV_N_];       // [T, 3*HID]  (q | k | v)
__device__ float g_q   [NH_ * T_ * D_];     // [h][t][d] post norm+rope
__device__ float g_k   [NH_ * T_ * D_];
__device__ float g_v   [NH_ * T_ * D_];
__device__ float g_attn[T_ * HID_];         // [t][h*D+d]

// ---------------------------------------------------------------------------
// SGEMM: C[M,N] = A[M,K] @ B[K,N], all row-major, fp32.
// 128x128 block tile, BK=8, 8x8 per-thread microtile, 256 threads.
// Requires M%128==0, N%128==0, K%8==0 (true for all our shapes).
// ---------------------------------------------------------------------------
__global__ __launch_bounds__(256) void sgemm128(
    const float* __restrict__ A, const float* __restrict__ B,
    float* __restrict__ C, int M, int N, int K)
{
    __shared__ float As[8][128];   // transposed A tile: As[k][m]
    __shared__ float Bs[8][128];   // Bs[k][n]

    const int tid  = threadIdx.x;
    const int brow = blockIdx.y;   // M tile
    const int bcol = blockIdx.x;   // N tile

    const float* Ablk = A + (size_t)brow * 128 * K;
    const float* Bblk = B + (size_t)bcol * 128;

    // A loader: 128 rows x 8 cols, float4 per thread
    const int arow = tid >> 1;            // 0..127
    const int acol = (tid & 1) * 4;       // 0 or 4
    // B loader: 8 rows x 128 cols
    const int brl  = tid >> 5;            // 0..7
    const int bcl  = (tid & 31) * 4;      // 0..124

    const int trow = (tid >> 4) * 8;      // 0..120
    const int tcol = (tid & 15) * 8;      // 0..120

    float acc[8][8];
    #pragma unroll
    for (int i = 0; i < 8; i++)
        #pragma unroll
        for (int j = 0; j < 8; j++) acc[i][j] = 0.f;

    for (int k0 = 0; k0 < K; k0 += 8) {
        float4 av = *(const float4*)(Ablk + (size_t)arow * K + k0 + acol);
        As[acol + 0][arow] = av.x;
        As[acol + 1][arow] = av.y;
        As[acol + 2][arow] = av.z;
        As[acol + 3][arow] = av.w;
        float4 bv = *(const float4*)(Bblk + (size_t)(k0 + brl) * N + bcl);
        *(float4*)&Bs[brl][bcl] = bv;
        __syncthreads();

        #pragma unroll
        for (int kk = 0; kk < 8; kk++) {
            float ra[8], rb[8];
            #pragma unroll
            for (int i = 0; i < 8; i++) ra[i] = As[kk][trow + i];
            #pragma unroll
            for (int j = 0; j < 8; j++) rb[j] = Bs[kk][tcol + j];
            #pragma unroll
            for (int i = 0; i < 8; i++)
                #pragma unroll
                for (int j = 0; j < 8; j++)
                    acc[i][j] = fmaf(ra[i], rb[j], acc[i][j]);
        }
        __syncthreads();
    }

    #pragma unroll
    for (int i = 0; i < 8; i++) {
        float* crow = C + (size_t)(brow * 128 + trow + i) * N + bcol * 128 + tcol;
        #pragma unroll
        for (int j = 0; j < 8; j += 4) {
            float4 v = make_float4(acc[i][j], acc[i][j+1], acc[i][j+2], acc[i][j+3]);
            *(float4*)(crow + j) = v;
        }
    }
}

// ---------------------------------------------------------------------------
// Per-(t,h) RMSNorm (q,k,v) + NeoX RoPE (q,k). 128 threads: thread i owns
// the pair (i, i+128) of the 256-dim head.
// ---------------------------------------------------------------------------
__global__ __launch_bounds__(128) void norm_rope_kernel(
    const int* __restrict__ positions,
    const float* __restrict__ qw, const float* __restrict__ kw)
{
    const int t = blockIdx.x;
    const int h = blockIdx.y;
    const int i = threadIdx.x;           // 0..127 (also the rope half-index)

    const float* base = g_qkv + (size_t)t * QKV_N_ + h * D_;
    const float q0 = base[i],            q1 = base[i + 128];
    const float k0 = base[HID_ + i],     k1 = base[HID_ + i + 128];
    const float v0 = base[2*HID_ + i],   v1 = base[2*HID_ + i + 128];

    // Sum of squares for q,k,v simultaneously
    float sq = q0*q0 + q1*q1;
    float sk = k0*k0 + k1*k1;
    float sv = v0*v0 + v1*v1;

    __shared__ float redq[4], redk[4], redv[4];
    #pragma unroll
    for (int off = 16; off > 0; off >>= 1) {
        sq += __shfl_xor_sync(0xffffffff, sq, off);
        sk += __shfl_xor_sync(0xffffffff, sk, off);
        sv += __shfl_xor_sync(0xffffffff, sv, off);
    }
    const int warp = i >> 5, lane = i & 31;
    if (lane == 0) { redq[warp] = sq; redk[warp] = sk; redv[warp] = sv; }
    __syncthreads();
    sq = redq[0] + redq[1] + redq[2] + redq[3];
    sk = redk[0] + redk[1] + redk[2] + redk[3];
    sv = redv[0] + redv[1] + redv[2] + redv[3];

    const float rq = rsqrtf(sq * (1.f / D_) + EPS_);
    const float rk = rsqrtf(sk * (1.f / D_) + EPS_);
    const float rv = rsqrtf(sv * (1.f / D_) + EPS_);

    const float qn0 = q0 * rq * qw[i], qn1 = q1 * rq * qw[i + 128];
    const float kn0 = k0 * rk * kw[i], kn1 = k1 * rk * kw[i + 128];

    // RoPE (NeoX): angle computed in double for accuracy at pos up to 2047
    const int pos = positions[t];
    const double inv_freq = exp(-(double)i * (2.0 / (double)D_) * log(10000.0));
    const double ang = (double)pos * inv_freq;
    const float c = (float)cos(ang);
    const float s = (float)sin(ang);

    float* qo = g_q + ((size_t)h * T_ + t) * D_;
    float* ko = g_k + ((size_t)h * T_ + t) * D_;
    float* vo = g_v + ((size_t)h * T_ + t) * D_;

    qo[i]       = qn0 * c - qn1 * s;
    qo[i + 128] = qn1 * c + qn0 * s;
    ko[i]       = kn0 * c - kn1 * s;
    ko[i + 128] = kn1 * c + kn0 * s;
    vo[i]       = v0 * rv;
    vo[i + 128] = v1 * rv;
}

// ---------------------------------------------------------------------------
// Causal attention, no score scaling (matches reference), online softmax.
// Grid: (T/8, NH). Block: 256 threads = 8 warps; warp w owns query
// qt = blockIdx.x*8 + w of head blockIdx.y. 16-key smem staging of K and V.
// ---------------------------------------------------------------------------
__global__ __launch_bounds__(256) void attn_kernel()
{
    __shared__ float Ks[16][256];
    __shared__ float Vs[16][256];

    const int h    = blockIdx.y;
    const int warp = threadIdx.x >> 5;
    const int lane = threadIdx.x & 31;
    const int qt   = blockIdx.x * 8 + warp;

    const float* qptr = g_q + ((size_t)h * T_ + qt) * D_;
    float qreg[8];
    #pragma unroll
    for (int j = 0; j < 8; j++) qreg[j] = qptr[lane + 32 * j];

    float m = -1e30f, l = 0.f;
    float o[8];
    #pragma unroll
    for (int j = 0; j < 8; j++) o[j] = 0.f;

    const int kmax   = blockIdx.x * 8 + 7;          // max key any warp needs
    const int ntiles = (kmax + 16) / 16;            // ceil((kmax+1)/16)

    // staging indices: each thread loads 16 consecutive floats per matrix
    const int srow = threadIdx.x >> 4;              // 0..15
    const int scol = (threadIdx.x & 15) * 16;       // 0..240

    for (int tile = 0; tile < ntiles; tile++) {
        const int base = tile * 16;
        {
            const float* kp = g_k + ((size_t)h * T_ + base + srow) * D_ + scol;
            const float* vp = g_v + ((size_t)h * T_ + base + srow) * D_ + scol;
            #pragma unroll
            for (int c = 0; c < 4; c++) {
                *(float4*)&Ks[srow][scol + 4*c] = *(const float4*)(kp + 4*c);
                *(float4*)&Vs[srow][scol + 4*c] = *(const float4*)(vp + 4*c);
            }
        }
        __syncthreads();

        const int lim = min(16, qt - base + 1);     // causal limit within tile
        for (int kk = 0; kk < lim; kk++) {
            float part = 0.f;
            #pragma unroll
            for (int j = 0; j < 8; j++)
                part = fmaf(qreg[j], Ks[kk][lane + 32 * j], part);
            #pragma unroll
            for (int off = 16; off > 0; off >>= 1)
                part += __shfl_xor_sync(0xffffffff, part, off);
            const float s = part;

            const float mnew  = fmaxf(m, s);
            const float p     = __expf(s - mnew);
            const float alpha = __expf(m - mnew);
            l = l * alpha + p;
            #pragma unroll
            for (int j = 0; j < 8; j++)
                o[j] = fmaf(o[j], alpha, p * Vs[kk][lane + 32 * j]);
            m = mnew;
        }
        __syncthreads();
    }

    const float inv = 1.f / l;
    float* op = g_attn + (size_t)qt * HID_ + h * D_;
    #pragma unroll
    for (int j = 0; j < 8; j++) op[lane + 32 * j] = o[j] * inv;
}

// ---------------------------------------------------------------------------
// Launch
// ---------------------------------------------------------------------------
extern "C" void kernel_launch(void* const* d_in, const int* in_sizes, int n_in,
                              void* d_out, int out_size)
{
    const float* hidden    = (const float*)d_in[0];
    const int*   positions = (const int*)  d_in[1];
    const float* w_qkv     = (const float*)d_in[2];
    const float* w_o       = (const float*)d_in[3];
    const float* q_norm_w  = (const float*)d_in[4];
    const float* k_norm_w  = (const float*)d_in[5];
    float* out = (float*)d_out;

    float *qkv_ptr = nullptr, *attn_ptr = nullptr;
    cudaGetSymbolAddress((void**)&qkv_ptr,  g_qkv);
    cudaGetSymbolAddress((void**)&attn_ptr, g_attn);

    // 1) QKV projection: [2048,4096] @ [4096,12288]
    sgemm128<<<dim3(QKV_N_ / 128, T_ / 128), 256>>>(hidden, w_qkv, qkv_ptr,
                                                    T_, QKV_N_, HID_);
    // 2) RMSNorm + RoPE
    norm_rope_kernel<<<dim3(T_, NH_), 128>>>(positions, q_norm_w, k_norm_w);

    // 3) Causal attention
    attn_kernel<<<dim3(T_ / 8, NH_), 256>>>();

    // 4) Output projection: [2048,4096] @ [4096,4096]
    sgemm128<<<dim3(HID_ / 128, T_ / 128), 256>>>(attn_ptr, w_o, out,
                                                  T_, HID_, HID_);
}

// round 3
// speedup vs baseline: 1.2426x; 1.2426x over previous
#include <cuda_runtime.h>
#include <math.h>
#include <stdint.h>

// Problem constants
#define T_   2048
#define HID_ 4096
#define NH_  16
#define D_   256
#define QKV_N_ (3 * HID_)   // 12288
#define EPS_ 1e-6f

// ---------------------------------------------------------------------------
// Scratch (device globals — no allocation allowed)
// ---------------------------------------------------------------------------
__device__ float g_qkv [T_ * QKV_N_];       // [T, 3*HID]  (q | k | v)
__device__ float g_q   [NH_ * T_ * D_];     // [h][t][d] post norm+rope
__device__ float g_k   [NH_ * T_ * D_];
__device__ float g_v   [NH_ * T_ * D_];
__device__ float g_attn[T_ * HID_];         // [t][h*D+d]
__device__ float2 g_rope[T_ * (D_ / 2)];    // per (t, i) cos/sin

// ---------------------------------------------------------------------------
// Helpers: tf32 convert + mma.sync
// ---------------------------------------------------------------------------
__device__ __forceinline__ uint32_t f2tf(float f) {
    uint32_t u;
    asm("cvt.rna.tf32.f32 %0, %1;" : "=r"(u) : "f"(f));
    return u;
}

__device__ __forceinline__ void split_tf32(float x, uint32_t& big, uint32_t& sml) {
    big = f2tf(x);
    sml = f2tf(x - __uint_as_float(big));
}

__device__ __forceinline__ void mma_tf32(float c[4],
                                         uint32_t a0, uint32_t a1, uint32_t a2, uint32_t a3,
                                         uint32_t b0, uint32_t b1) {
    asm volatile(
        "mma.sync.aligned.m16n8k8.row.col.f32.tf32.tf32.f32 "
        "{%0,%1,%2,%3}, {%4,%5,%6,%7}, {%8,%9}, {%0,%1,%2,%3};"
        : "+f"(c[0]), "+f"(c[1]), "+f"(c[2]), "+f"(c[3])
        : "r"(a0), "r"(a1), "r"(a2), "r"(a3), "r"(b0), "r"(b1));
}

#define CP_ASYNC16(smem_u32, gptr) \
    asm volatile("cp.async.cg.shared.global [%0], [%1], 16;" :: "r"(smem_u32), "l"(gptr))
#define CP_COMMIT() asm volatile("cp.async.commit_group;")
#define CP_WAIT(n)  asm volatile("cp.async.wait_group %0;" :: "n"(n))

// ---------------------------------------------------------------------------
// TF32 tensor-core GEMM with fp32-accuracy 3xTF32 split.
// C[M,N] = A[M,K] @ B[K,N], row-major fp32. 128x128 block, BK=16,
// 8 warps (2x4), warp tile 64x32, m16n8k8 mma. Double-buffered cp.async.
// Requires M%128==0, N%128==0, K%16==0 (true here).
// ---------------------------------------------------------------------------
__global__ __launch_bounds__(256) void gemm_tf32(
    const float* __restrict__ A, const float* __restrict__ B,
    float* __restrict__ C, int M, int N, int K)
{
    __shared__ float As[2][128][20];   // padded: frag loads hit 32 distinct banks
    __shared__ float Bs[2][16][136];   // padded: 8k+n distinct banks

    const int tid  = threadIdx.x;
    const int bm   = blockIdx.y * 128;
    const int bn   = blockIdx.x * 128;
    const int wid  = tid >> 5, lane = tid & 31;
    const int wm   = (wid >> 2) * 64;       // warp M offset (0,64)
    const int wn   = (wid & 3)  * 32;       // warp N offset (0..96)
    const int g    = lane >> 2;             // 0..7
    const int tig  = lane & 3;              // 0..3

    float acc[4][4][4];
    #pragma unroll
    for (int i = 0; i < 4; i++)
        #pragma unroll
        for (int j = 0; j < 4; j++)
            #pragma unroll
            for (int r = 0; r < 4; r++) acc[i][j][r] = 0.f;

    const int ntiles = K >> 4;   // BK = 16

    // ---- async loaders: A tile 128x16 (512 f4), B tile 16x128 (512 f4) ----
    auto load_tile = [&](int buf, int k0) {
        #pragma unroll
        for (int i = tid; i < 512; i += 256) {
            int m = i >> 2, c = (i & 3) * 4;
            uint32_t dst = (uint32_t)__cvta_generic_to_shared(&As[buf][m][c]);
            CP_ASYNC16(dst, A + (size_t)(bm + m) * K + k0 + c);
        }
        #pragma unroll
        for (int i = tid; i < 512; i += 256) {
            int k = i >> 5, c = (i & 31) * 4;
            uint32_t dst = (uint32_t)__cvta_generic_to_shared(&Bs[buf][k][c]);
            CP_ASYNC16(dst, B + (size_t)(k0 + k) * N + bn + c);
        }
        CP_COMMIT();
    };

    load_tile(0, 0);

    for (int t = 0; t < ntiles; t++) {
        const int buf = t & 1;
        if (t + 1 < ntiles) {
            load_tile(buf ^ 1, (t + 1) << 4);
            CP_WAIT(1);
        } else {
            CP_WAIT(0);
        }
        __syncthreads();

        #pragma unroll
        for (int ks = 0; ks < 16; ks += 8) {
            uint32_t abig[4][4], asml[4][4];
            uint32_t bbig[4][2], bsml[4][2];
            #pragma unroll
            for (int mf = 0; mf < 4; mf++) {
                const int r0 = wm + mf * 16 + g;
                split_tf32(As[buf][r0    ][ks + tig    ], abig[mf][0], asml[mf][0]);
                split_tf32(As[buf][r0 + 8][ks + tig    ], abig[mf][1], asml[mf][1]);
                split_tf32(As[buf][r0    ][ks + tig + 4], abig[mf][2], asml[mf][2]);
                split_tf32(As[buf][r0 + 8][ks + tig + 4], abig[mf][3], asml[mf][3]);
            }
            #pragma unroll
            for (int nf = 0; nf < 4; nf++) {
                const int c0 = wn + nf * 8 + g;
                split_tf32(Bs[buf][ks + tig    ][c0], bbig[nf][0], bsml[nf][0]);
                split_tf32(Bs[buf][ks + tig + 4][c0], bbig[nf][1], bsml[nf][1]);
            }
            #pragma unroll
            for (int mf = 0; mf < 4; mf++)
                #pragma unroll
                for (int nf = 0; nf < 4; nf++) {
                    // 3xTF32: small cross-terms first, then big*big
                    mma_tf32(acc[mf][nf], asml[mf][0], asml[mf][1], asml[mf][2], asml[mf][3],
                             bbig[nf][0], bbig[nf][1]);
                    mma_tf32(acc[mf][nf], abig[mf][0], abig[mf][1], abig[mf][2], abig[mf][3],
                             bsml[nf][0], bsml[nf][1]);
                    mma_tf32(acc[mf][nf], abig[mf][0], abig[mf][1], abig[mf][2], abig[mf][3],
                             bbig[nf][0], bbig[nf][1]);
                }
        }
        __syncthreads();
    }

    // ---- epilogue ----
    #pragma unroll
    for (int mf = 0; mf < 4; mf++) {
        #pragma unroll
        for (int nf = 0; nf < 4; nf++) {
            const int r0 = bm + wm + mf * 16 + g;
            const int c0 = bn + wn + nf * 8 + tig * 2;
            *(float2*)(C + (size_t)r0 * N + c0)       = make_float2(acc[mf][nf][0], acc[mf][nf][1]);
            *(float2*)(C + (size_t)(r0 + 8) * N + c0) = make_float2(acc[mf][nf][2], acc[mf][nf][3]);
        }
    }
}

// ---------------------------------------------------------------------------
// RoPE table: cos/sin for (t, i). Angle via double exp (accurate inv_freq),
// trig in float. Removes 16x per-head redundancy and double cos/sin.
// ---------------------------------------------------------------------------
__global__ __launch_bounds__(128) void rope_table_kernel(const int* __restrict__ positions)
{
    const int t = blockIdx.x;
    const int i = threadIdx.x;    // 0..127
    const int pos = positions[t];
    const double inv_freq = exp(-(double)i * (2.0 / (double)D_) * log(10000.0));
    const float ang = (float)((double)pos * inv_freq);
    float s, c;
    sincosf(ang, &s, &c);
    g_rope[t * 128 + i] = make_float2(c, s);
}

// ---------------------------------------------------------------------------
// Per-(t,h) RMSNorm (q,k,v) + NeoX RoPE (q,k). 128 threads: thread i owns
// the pair (i, i+128) of the 256-dim head.
// ---------------------------------------------------------------------------
__global__ __launch_bounds__(128) void norm_rope_kernel(
    const float* __restrict__ qw, const float* __restrict__ kw)
{
    const int t = blockIdx.x;
    const int h = blockIdx.y;
    const int i = threadIdx.x;           // 0..127 (also the rope half-index)

    const float* base = g_qkv + (size_t)t * QKV_N_ + h * D_;
    const float q0 = base[i],            q1 = base[i + 128];
    const float k0 = base[HID_ + i],     k1 = base[HID_ + i + 128];
    const float v0 = base[2*HID_ + i],   v1 = base[2*HID_ + i + 128];

    float sq = q0*q0 + q1*q1;
    float sk = k0*k0 + k1*k1;
    float sv = v0*v0 + v1*v1;

    __shared__ float redq[4], redk[4], redv[4];
    #pragma unroll
    for (int off = 16; off > 0; off >>= 1) {
        sq += __shfl_xor_sync(0xffffffff, sq, off);
        sk += __shfl_xor_sync(0xffffffff, sk, off);
        sv += __shfl_xor_sync(0xffffffff, sv, off);
    }
    const int warp = i >> 5, lane = i & 31;
    if (lane == 0) { redq[warp] = sq; redk[warp] = sk; redv[warp] = sv; }
    __syncthreads();
    sq = redq[0] + redq[1] + redq[2] + redq[3];
    sk = redk[0] + redk[1] + redk[2] + redk[3];
    sv = redv[0] + redv[1] + redv[2] + redv[3];

    const float rq = rsqrtf(sq * (1.f / D_) + EPS_);
    const float rk = rsqrtf(sk * (1.f / D_) + EPS_);
    const float rv = rsqrtf(sv * (1.f / D_) + EPS_);

    const float qn0 = q0 * rq * qw[i], qn1 = q1 * rq * qw[i + 128];
    const float kn0 = k0 * rk * kw[i], kn1 = k1 * rk * kw[i + 128];

    const float2 cs = g_rope[t * 128 + i];
    const float c = cs.x, s = cs.y;

    float* qo = g_q + ((size_t)h * T_ + t) * D_;
    float* ko = g_k + ((size_t)h * T_ + t) * D_;
    float* vo = g_v + ((size_t)h * T_ + t) * D_;

    qo[i]       = qn0 * c - qn1 * s;
    qo[i + 128] = qn1 * c + qn0 * s;
    ko[i]       = kn0 * c - kn1 * s;
    ko[i + 128] = kn1 * c + kn0 * s;
    vo[i]       = v0 * rv;
    vo[i + 128] = v1 * rv;
}

// ---------------------------------------------------------------------------
// Causal attention, no score scaling (matches reference), online softmax.
// Grid: (T/8, NH). Block: 256 threads = 8 warps; warp w owns query
// qt = blockIdx.x*8 + w of head blockIdx.y. 16-key smem staging of K and V.
// ---------------------------------------------------------------------------
__global__ __launch_bounds__(256) void attn_kernel()
{
    __shared__ float Ks[16][256];
    __shared__ float Vs[16][256];

    const int h    = blockIdx.y;
    const int warp = threadIdx.x >> 5;
    const int lane = threadIdx.x & 31;
    const int qt   = blockIdx.x * 8 + warp;

    const float* qptr = g_q + ((size_t)h * T_ + qt) * D_;
    float qreg[8];
    #pragma unroll
    for (int j = 0; j < 8; j++) qreg[j] = qptr[lane + 32 * j];

    float m = -1e30f, l = 0.f;
    float o[8];
    #pragma unroll
    for (int j = 0; j < 8; j++) o[j] = 0.f;

    const int kmax   = blockIdx.x * 8 + 7;
    const int ntiles = (kmax + 16) / 16;

    const int srow = threadIdx.x >> 4;
    const int scol = (threadIdx.x & 15) * 16;

    for (int tile = 0; tile < ntiles; tile++) {
        const int base = tile * 16;
        {
            const float* kp = g_k + ((size_t)h * T_ + base + srow) * D_ + scol;
            const float* vp = g_v + ((size_t)h * T_ + base + srow) * D_ + scol;
            #pragma unroll
            for (int c = 0; c < 4; c++) {
                *(float4*)&Ks[srow][scol + 4*c] = *(const float4*)(kp + 4*c);
                *(float4*)&Vs[srow][scol + 4*c] = *(const float4*)(vp + 4*c);
            }
        }
        __syncthreads();

        const int lim = min(16, qt - base + 1);
        for (int kk = 0; kk < lim; kk++) {
            float part = 0.f;
            #pragma unroll
            for (int j = 0; j < 8; j++)
                part = fmaf(qreg[j], Ks[kk][lane + 32 * j], part);
            #pragma unroll
            for (int off = 16; off > 0; off >>= 1)
                part += __shfl_xor_sync(0xffffffff, part, off);
            const float s = part;

            const float mnew  = fmaxf(m, s);
            const float p     = __expf(s - mnew);
            const float alpha = __expf(m - mnew);
            l = l * alpha + p;
            #pragma unroll
            for (int j = 0; j < 8; j++)
                o[j] = fmaf(o[j], alpha, p * Vs[kk][lane + 32 * j]);
            m = mnew;
        }
        __syncthreads();
    }

    const float inv = 1.f / l;
    float* op = g_attn + (size_t)qt * HID_ + h * D_;
    #pragma unroll
    for (int j = 0; j < 8; j++) op[lane + 32 * j] = o[j] * inv;
}

// ---------------------------------------------------------------------------
// Launch
// ---------------------------------------------------------------------------
extern "C" void kernel_launch(void* const* d_in, const int* in_sizes, int n_in,
                              void* d_out, int out_size)
{
    const float* hidden    = (const float*)d_in[0];
    const int*   positions = (const int*)  d_in[1];
    const float* w_qkv     = (const float*)d_in[2];
    const float* w_o       = (const float*)d_in[3];
    const float* q_norm_w  = (const float*)d_in[4];
    const float* k_norm_w  = (const float*)d_in[5];
    float* out = (float*)d_out;

    float *qkv_ptr = nullptr, *attn_ptr = nullptr;
    cudaGetSymbolAddress((void**)&qkv_ptr,  g_qkv);
    cudaGetSymbolAddress((void**)&attn_ptr, g_attn);

    // RoPE cos/sin table (independent of GEMM — overlaps trivially)
    rope_table_kernel<<<T_, 128>>>(positions);

    // 1) QKV projection: [2048,4096] @ [4096,12288] (tf32 tensor cores, 3x split)
    gemm_tf32<<<dim3(QKV_N_ / 128, T_ / 128), 256>>>(hidden, w_qkv, qkv_ptr,
                                                     T_, QKV_N_, HID_);
    // 2) RMSNorm + RoPE
    norm_rope_kernel<<<dim3(T_, NH_), 128>>>(q_norm_w, k_norm_w);

    // 3) Causal attention
    attn_kernel<<<dim3(T_ / 8, NH_), 256>>>();

    // 4) Output projection: [2048,4096] @ [4096,4096]
    gemm_tf32<<<dim3(HID_ / 128, T_ / 128), 256>>>(attn_ptr, w_o, out,
                                                   T_, HID_, HID_);
}

// round 4
// speedup vs baseline: 3.5375x; 2.8470x over previous
#include <cuda_runtime.h>
#include <cuda_bf16.h>
#include <math.h>
#include <stdint.h>

// Problem constants
#define T_   2048
#define HID_ 4096
#define NH_  16
#define D_   256
#define QKV_N_ (3 * HID_)   // 12288
#define EPS_ 1e-6f

// ---------------------------------------------------------------------------
// Scratch (device globals — no allocation allowed)
// Packed format: uint32 = (bf16(lo) << 16) | bf16(hi), hi = bf16(x), lo = bf16(x-hi)
// ---------------------------------------------------------------------------
__device__ float    g_qkv   [T_ * QKV_N_];        // fp32 qkv projection result
__device__ uint32_t g_hid32 [T_ * HID_];          // packed hidden_states
__device__ uint32_t g_wqkv32[HID_ * QKV_N_];      // packed w_qkv
__device__ uint32_t g_wo32  [HID_ * HID_];        // packed w_o
__device__ uint32_t g_q32   [NH_ * T_ * D_];      // packed q (post norm+rope), [h][t][d]
__device__ uint32_t g_k32   [NH_ * T_ * D_];
__device__ uint32_t g_v32   [NH_ * T_ * D_];
__device__ uint32_t g_attn32[T_ * HID_];          // packed attention output [t][h*D+d]
__device__ float2   g_rope  [T_ * (D_ / 2)];

// ---------------------------------------------------------------------------
// Helpers
// ---------------------------------------------------------------------------
__device__ __forceinline__ uint32_t pack_split(float x) {
    __nv_bfloat16 hb = __float2bfloat16(x);
    float hf = __bfloat162float(hb);
    __nv_bfloat16 lb = __float2bfloat16(x - hf);
    return ((uint32_t)__bfloat16_as_ushort(lb) << 16) | (uint32_t)__bfloat16_as_ushort(hb);
}

// From packed pair (u0 = element k, u1 = element k+1):
//   main bf16x2 reg = bytes [u1.b1 u1.b0 u0.b1 u0.b0] = perm 0x5410
//   resid           = perm 0x7632
#define MAIN2(u0, u1) __byte_perm((u0), (u1), 0x5410)
#define RESID2(u0, u1) __byte_perm((u0), (u1), 0x7632)

__device__ __forceinline__ void mma_bf16(float c[4],
                                         uint32_t a0, uint32_t a1, uint32_t a2, uint32_t a3,
                                         uint32_t b0, uint32_t b1) {
    asm volatile(
        "mma.sync.aligned.m16n8k16.row.col.f32.bf16.bf16.f32 "
        "{%0,%1,%2,%3}, {%4,%5,%6,%7}, {%8,%9}, {%0,%1,%2,%3};"
        : "+f"(c[0]), "+f"(c[1]), "+f"(c[2]), "+f"(c[3])
        : "r"(a0), "r"(a1), "r"(a2), "r"(a3), "r"(b0), "r"(b1));
}

#define CP_ASYNC16(smem_u32, gptr) \
    asm volatile("cp.async.cg.shared.global [%0], [%1], 16;" :: "r"(smem_u32), "l"(gptr))
#define CP_COMMIT() asm volatile("cp.async.commit_group;")
#define CP_WAIT(n)  asm volatile("cp.async.wait_group %0;" :: "n"(n))

// ---------------------------------------------------------------------------
// Elementwise split-pack: fp32 -> packed bf16 hi/lo
// ---------------------------------------------------------------------------
__global__ __launch_bounds__(256) void split_pack_kernel(
    const float* __restrict__ src, uint32_t* __restrict__ dst, int n4)
{
    int i = blockIdx.x * 256 + threadIdx.x;
    int stride = gridDim.x * 256;
    for (; i < n4; i += stride) {
        float4 v = ((const float4*)src)[i];
        uint4 o;
        o.x = pack_split(v.x); o.y = pack_split(v.y);
        o.z = pack_split(v.z); o.w = pack_split(v.w);
        ((uint4*)dst)[i] = o;
    }
}

// ---------------------------------------------------------------------------
// bf16-split tensor GEMM: C_fp32[M,N] = A32[M,K] @ B32[K,N]
// 128x128 tile, BK=16, 8 warps (2x4), warp 64x32, m16n8k16, 3-mma split.
// ---------------------------------------------------------------------------
__global__ __launch_bounds__(256) void gemm_bf16s(
    const uint32_t* __restrict__ A, const uint32_t* __restrict__ B,
    float* __restrict__ C, int M, int N, int K)
{
    __shared__ uint32_t As[2][128][20];   // [m][k], pad 20 (80B, 16B-mult)
    __shared__ uint32_t Bs[2][16][136];   // [k][n], pad 136 (544B, 16B-mult)

    const int tid  = threadIdx.x;
    const int bm   = blockIdx.y * 128;
    const int bn   = blockIdx.x * 128;
    const int wid  = tid >> 5, lane = tid & 31;
    const int wm   = (wid >> 2) * 64;
    const int wn   = (wid & 3)  * 32;
    const int g    = lane >> 2;
    const int tig  = lane & 3;

    float acc[4][4][4];
    #pragma unroll
    for (int i = 0; i < 4; i++)
        #pragma unroll
        for (int j = 0; j < 4; j++)
            #pragma unroll
            for (int r = 0; r < 4; r++) acc[i][j][r] = 0.f;

    const int ntiles = K >> 4;

    auto load_tile = [&](int buf, int k0) {
        #pragma unroll
        for (int i = tid; i < 512; i += 256) {      // A: 128 rows x 4 chunks
            int m = i >> 2, c = (i & 3) * 4;
            uint32_t dst = (uint32_t)__cvta_generic_to_shared(&As[buf][m][c]);
            CP_ASYNC16(dst, A + (size_t)(bm + m) * K + k0 + c);
        }
        #pragma unroll
        for (int i = tid; i < 512; i += 256) {      // B: 16 rows x 32 chunks
            int k = i >> 5, c = (i & 31) * 4;
            uint32_t dst = (uint32_t)__cvta_generic_to_shared(&Bs[buf][k][c]);
            CP_ASYNC16(dst, B + (size_t)(k0 + k) * N + bn + c);
        }
        CP_COMMIT();
    };

    load_tile(0, 0);

    for (int t = 0; t < ntiles; t++) {
        const int buf = t & 1;
        if (t + 1 < ntiles) { load_tile(buf ^ 1, (t + 1) << 4); CP_WAIT(1); }
        else                { CP_WAIT(0); }
        __syncthreads();

        uint32_t Ah[4][4], Al[4][4], Bh[4][2], Bl[4][2];
        #pragma unroll
        for (int mf = 0; mf < 4; mf++) {
            const int r0 = wm + mf * 16 + g;
            uint2 u0 = *(const uint2*)&As[buf][r0    ][2 * tig];
            uint2 u1 = *(const uint2*)&As[buf][r0 + 8][2 * tig];
            uint2 u2 = *(const uint2*)&As[buf][r0    ][2 * tig + 8];
            uint2 u3 = *(const uint2*)&As[buf][r0 + 8][2 * tig + 8];
            Ah[mf][0] = MAIN2(u0.x, u0.y);  Al[mf][0] = RESID2(u0.x, u0.y);
            Ah[mf][1] = MAIN2(u1.x, u1.y);  Al[mf][1] = RESID2(u1.x, u1.y);
            Ah[mf][2] = MAIN2(u2.x, u2.y);  Al[mf][2] = RESID2(u2.x, u2.y);
            Ah[mf][3] = MAIN2(u3.x, u3.y);  Al[mf][3] = RESID2(u3.x, u3.y);
        }
        #pragma unroll
        for (int nf = 0; nf < 4; nf++) {
            const int n0 = wn + nf * 8 + g;
            uint32_t v0 = Bs[buf][2 * tig    ][n0];
            uint32_t v1 = Bs[buf][2 * tig + 1][n0];
            uint32_t v2 = Bs[buf][2 * tig + 8][n0];
            uint32_t v3 = Bs[buf][2 * tig + 9][n0];
            Bh[nf][0] = MAIN2(v0, v1);  Bl[nf][0] = RESID2(v0, v1);
            Bh[nf][1] = MAIN2(v2, v3);  Bl[nf][1] = RESID2(v2, v3);
        }
        #pragma unroll
        for (int mf = 0; mf < 4; mf++)
            #pragma unroll
            for (int nf = 0; nf < 4; nf++) {
                mma_bf16(acc[mf][nf], Ah[mf][0], Ah[mf][1], Ah[mf][2], Ah[mf][3], Bl[nf][0], Bl[nf][1]);
                mma_bf16(acc[mf][nf], Al[mf][0], Al[mf][1], Al[mf][2], Al[mf][3], Bh[nf][0], Bh[nf][1]);
                mma_bf16(acc[mf][nf], Ah[mf][0], Ah[mf][1], Ah[mf][2], Ah[mf][3], Bh[nf][0], Bh[nf][1]);
            }
        __syncthreads();
    }

    #pragma unroll
    for (int mf = 0; mf < 4; mf++)
        #pragma unroll
        for (int nf = 0; nf < 4; nf++) {
            const int r0 = bm + wm + mf * 16 + g;
            const int c0 = bn + wn + nf * 8 + tig * 2;
            *(float2*)(C + (size_t)r0 * N + c0)       = make_float2(acc[mf][nf][0], acc[mf][nf][1]);
            *(float2*)(C + (size_t)(r0 + 8) * N + c0) = make_float2(acc[mf][nf][2], acc[mf][nf][3]);
        }
}

// ---------------------------------------------------------------------------
// RoPE cos/sin table
// ---------------------------------------------------------------------------
__global__ __launch_bounds__(128) void rope_table_kernel(const int* __restrict__ positions)
{
    const int t = blockIdx.x;
    const int i = threadIdx.x;
    const int pos = positions[t];
    const double inv_freq = exp(-(double)i * (2.0 / (double)D_) * log(10000.0));
    const float ang = (float)((double)pos * inv_freq);
    float s, c;
    sincosf(ang, &s, &c);
    g_rope[t * 128 + i] = make_float2(c, s);
}

// ---------------------------------------------------------------------------
// RMSNorm + RoPE; writes packed bf16-split q/k/v.
// ---------------------------------------------------------------------------
__global__ __launch_bounds__(128) void norm_rope_kernel(
    const float* __restrict__ qw, const float* __restrict__ kw)
{
    const int t = blockIdx.x;
    const int h = blockIdx.y;
    const int i = threadIdx.x;

    const float* base = g_qkv + (size_t)t * QKV_N_ + h * D_;
    const float q0 = base[i],            q1 = base[i + 128];
    const float k0 = base[HID_ + i],     k1 = base[HID_ + i + 128];
    const float v0 = base[2*HID_ + i],   v1 = base[2*HID_ + i + 128];

    float sq = q0*q0 + q1*q1;
    float sk = k0*k0 + k1*k1;
    float sv = v0*v0 + v1*v1;

    __shared__ float redq[4], redk[4], redv[4];
    #pragma unroll
    for (int off = 16; off > 0; off >>= 1) {
        sq += __shfl_xor_sync(0xffffffff, sq, off);
        sk += __shfl_xor_sync(0xffffffff, sk, off);
        sv += __shfl_xor_sync(0xffffffff, sv, off);
    }
    const int warp = i >> 5, lane = i & 31;
    if (lane == 0) { redq[warp] = sq; redk[warp] = sk; redv[warp] = sv; }
    __syncthreads();
    sq = redq[0] + redq[1] + redq[2] + redq[3];
    sk = redk[0] + redk[1] + redk[2] + redk[3];
    sv = redv[0] + redv[1] + redv[2] + redv[3];

    const float rq = rsqrtf(sq * (1.f / D_) + EPS_);
    const float rk = rsqrtf(sk * (1.f / D_) + EPS_);
    const float rv = rsqrtf(sv * (1.f / D_) + EPS_);

    const float qn0 = q0 * rq * qw[i], qn1 = q1 * rq * qw[i + 128];
    const float kn0 = k0 * rk * kw[i], kn1 = k1 * rk * kw[i + 128];

    const float2 cs = g_rope[t * 128 + i];
    const float c = cs.x, s = cs.y;

    uint32_t* qo = g_q32 + ((size_t)h * T_ + t) * D_;
    uint32_t* ko = g_k32 + ((size_t)h * T_ + t) * D_;
    uint32_t* vo = g_v32 + ((size_t)h * T_ + t) * D_;

    qo[i]       = pack_split(qn0 * c - qn1 * s);
    qo[i + 128] = pack_split(qn1 * c + qn0 * s);
    ko[i]       = pack_split(kn0 * c - kn1 * s);
    ko[i + 128] = pack_split(kn1 * c + kn0 * s);
    vo[i]       = pack_split(v0 * rv);
    vo[i + 128] = pack_split(v1 * rv);
}

// ---------------------------------------------------------------------------
// Tensor-core flash attention, bf16-split, no score scaling (matches ref).
// Grid (T/32, NH), 256 threads (8 warps). 32q x 32k tiles.
// Dynamic smem layout (uint32 units):
//   Qs  [32][260]
//   Ks  [2][32][260]
//   Vs  [2][32][260]
//   Ss  [32][36]   (float scores, reused as packed P)
//   mS[32], lS[32], aS[32]
// ---------------------------------------------------------------------------
#define QSTRIDE 260
#define SSTRIDE 36
#define OFF_Q   0
#define OFF_K   (32 * QSTRIDE)
#define OFF_V   (OFF_K + 2 * 32 * QSTRIDE)
#define OFF_S   (OFF_V + 2 * 32 * QSTRIDE)
#define OFF_M   (OFF_S + 32 * SSTRIDE)
#define OFF_L   (OFF_M + 32)
#define OFF_A   (OFF_L + 32)
#define ATTN_SMEM_BYTES ((OFF_A + 32) * 4)

__global__ __launch_bounds__(256) void attn_kernel()
{
    extern __shared__ uint32_t sm[];
    uint32_t* Qs = sm + OFF_Q;
    uint32_t* Ks = sm + OFF_K;
    uint32_t* Vs = sm + OFF_V;
    float*    Ss = (float*)(sm + OFF_S);
    float*    mS = (float*)(sm + OFF_M);
    float*    lS = (float*)(sm + OFF_L);
    float*    aS = (float*)(sm + OFF_A);

    const int bx = blockIdx.x;         // q tile
    const int h  = blockIdx.y;
    const int q0 = bx * 32;
    const int ntiles = bx + 1;

    const int tid  = threadIdx.x;
    const int wid  = tid >> 5, lane = tid & 31;
    const int g    = lane >> 2;        // 0..7
    const int tig  = lane & 3;         // 0..3

    // ---- issue Q load + KV tile 0 as group 0 ----
    {
        const uint32_t* qsrc = g_q32 + ((size_t)h * T_ + q0) * D_;
        #pragma unroll
        for (int i = tid; i < 2048; i += 256) {     // 32 rows x 64 chunks
            int r = i >> 6, c = (i & 63) * 4;
            uint32_t dst = (uint32_t)__cvta_generic_to_shared(&Qs[r * QSTRIDE + c]);
            CP_ASYNC16(dst, qsrc + (size_t)r * D_ + c);
        }
    }
    auto load_kv = [&](int buf, int t) {
        const size_t base = ((size_t)h * T_ + t * 32) * D_;
        uint32_t* kd = Ks + buf * 32 * QSTRIDE;
        uint32_t* vd = Vs + buf * 32 * QSTRIDE;
        #pragma unroll
        for (int i = tid; i < 2048; i += 256) {
            int r = i >> 6, c = (i & 63) * 4;
            uint32_t dk = (uint32_t)__cvta_generic_to_shared(&kd[r * QSTRIDE + c]);
            CP_ASYNC16(dk, g_k32 + base + (size_t)r * D_ + c);
            uint32_t dv = (uint32_t)__cvta_generic_to_shared(&vd[r * QSTRIDE + c]);
            CP_ASYNC16(dv, g_v32 + base + (size_t)r * D_ + c);
        }
        CP_COMMIT();
    };
    load_kv(0, 0);

    if (tid < 32) { mS[tid] = -1e30f; lS[tid] = 0.f; }

    // PV accumulators: warp = 16q x 64d (wq2 = wid>>2, wd = wid&3), 8 nfrags
    float oc[8][4];
    #pragma unroll
    for (int nf = 0; nf < 8; nf++)
        #pragma unroll
        for (int r = 0; r < 4; r++) oc[nf][r] = 0.f;

    const int wq = wid >> 2;           // QK: q group (0..1), rows wq*16..
    const int wk = wid & 3;            // QK: key group (0..3), keys wk*8..
    const int srow = tid >> 3;         // softmax row 0..31
    const int sl8  = tid & 7;          // softmax lane-in-row

    for (int t = 0; t < ntiles; t++) {
        const int buf = t & 1;
        if (t + 1 < ntiles) { load_kv(buf ^ 1, t + 1); CP_WAIT(1); }
        else                { CP_WAIT(0); }
        __syncthreads();

        // ---------------- QK: S[32x32] ----------------
        const uint32_t* Kb = Ks + buf * 32 * QSTRIDE;
        float c4[4] = {0.f, 0.f, 0.f, 0.f};
        #pragma unroll
        for (int ks = 0; ks < 16; ks++) {
            const int kc = ks * 16 + 2 * tig;
            uint2 ua0 = *(const uint2*)&Qs[(wq * 16 + g    ) * QSTRIDE + kc];
            uint2 ua1 = *(const uint2*)&Qs[(wq * 16 + g + 8) * QSTRIDE + kc];
            uint2 ua2 = *(const uint2*)&Qs[(wq * 16 + g    ) * QSTRIDE + kc + 8];
            uint2 ua3 = *(const uint2*)&Qs[(wq * 16 + g + 8) * QSTRIDE + kc + 8];
            uint32_t Ah0 = MAIN2(ua0.x, ua0.y), Al0 = RESID2(ua0.x, ua0.y);
            uint32_t Ah1 = MAIN2(ua1.x, ua1.y), Al1 = RESID2(ua1.x, ua1.y);
            uint32_t Ah2 = MAIN2(ua2.x, ua2.y), Al2 = RESID2(ua2.x, ua2.y);
            uint32_t Ah3 = MAIN2(ua3.x, ua3.y), Al3 = RESID2(ua3.x, ua3.y);
            uint2 ub0 = *(const uint2*)&Kb[(wk * 8 + g) * QSTRIDE + kc];
            uint2 ub1 = *(const uint2*)&Kb[(wk * 8 + g) * QSTRIDE + kc + 8];
            uint32_t Bh0 = MAIN2(ub0.x, ub0.y), Bl0 = RESID2(ub0.x, ub0.y);
            uint32_t Bh1 = MAIN2(ub1.x, ub1.y), Bl1 = RESID2(ub1.x, ub1.y);
            mma_bf16(c4, Ah0, Ah1, Ah2, Ah3, Bl0, Bl1);
            mma_bf16(c4, Al0, Al1, Al2, Al3, Bh0, Bh1);
            mma_bf16(c4, Ah0, Ah1, Ah2, Ah3, Bh0, Bh1);
        }
        {
            const int sc = wk * 8 + 2 * tig;
            Ss[(wq * 16 + g    ) * SSTRIDE + sc    ] = c4[0];
            Ss[(wq * 16 + g    ) * SSTRIDE + sc + 1] = c4[1];
            Ss[(wq * 16 + g + 8) * SSTRIDE + sc    ] = c4[2];
            Ss[(wq * 16 + g + 8) * SSTRIDE + sc + 1] = c4[3];
        }
        __syncthreads();

        // ---------------- softmax (online) ----------------
        {
            const int c0 = sl8 * 4;
            float4 sv = *(const float4*)&Ss[srow * SSTRIDE + c0];
            const bool lastmask = (t == bx);
            float s0 = sv.x, s1 = sv.y, s2 = sv.z, s3 = sv.w;
            bool v0 = !lastmask || (c0 + 0 <= srow);
            bool v1 = !lastmask || (c0 + 1 <= srow);
            bool v2 = !lastmask || (c0 + 2 <= srow);
            bool v3 = !lastmask || (c0 + 3 <= srow);
            float lmax = -1e30f;
            if (v0) lmax = fmaxf(lmax, s0);
            if (v1) lmax = fmaxf(lmax, s1);
            if (v2) lmax = fmaxf(lmax, s2);
            if (v3) lmax = fmaxf(lmax, s3);
            #pragma unroll
            for (int off = 4; off > 0; off >>= 1)
                lmax = fmaxf(lmax, __shfl_xor_sync(0xffffffff, lmax, off, 8));
            const float m_old = mS[srow];
            const float mnew  = fmaxf(m_old, lmax);
            float p0 = v0 ? __expf(s0 - mnew) : 0.f;
            float p1 = v1 ? __expf(s1 - mnew) : 0.f;
            float p2 = v2 ? __expf(s2 - mnew) : 0.f;
            float p3 = v3 ? __expf(s3 - mnew) : 0.f;
            float lsum = p0 + p1 + p2 + p3;
            #pragma unroll
            for (int off = 4; off > 0; off >>= 1)
                lsum += __shfl_xor_sync(0xffffffff, lsum, off, 8);
            uint32_t* Pp = (uint32_t*)&Ss[srow * SSTRIDE + c0];
            Pp[0] = pack_split(p0); Pp[1] = pack_split(p1);
            Pp[2] = pack_split(p2); Pp[3] = pack_split(p3);
            if (sl8 == 0) {
                const float alpha = __expf(m_old - mnew);
                mS[srow] = mnew;
                lS[srow] = lS[srow] * alpha + lsum;
                aS[srow] = alpha;
            }
        }
        __syncthreads();

        // ---------------- PV: O += P @ V ----------------
        {
            const int wq2 = wid >> 2, wd = wid & 3;
            const float a_lo = aS[wq2 * 16 + g];
            const float a_hi = aS[wq2 * 16 + g + 8];
            #pragma unroll
            for (int nf = 0; nf < 8; nf++) {
                oc[nf][0] *= a_lo; oc[nf][1] *= a_lo;
                oc[nf][2] *= a_hi; oc[nf][3] *= a_hi;
            }
            const uint32_t* Vb = Vs + buf * 32 * QSTRIDE;
            const uint32_t* Pu = (const uint32_t*)Ss;
            #pragma unroll
            for (int ks = 0; ks < 2; ks++) {
                const int kc = ks * 16 + 2 * tig;
                uint2 up0 = *(const uint2*)&Pu[(wq2 * 16 + g    ) * SSTRIDE + kc];
                uint2 up1 = *(const uint2*)&Pu[(wq2 * 16 + g + 8) * SSTRIDE + kc];
                uint2 up2 = *(const uint2*)&Pu[(wq2 * 16 + g    ) * SSTRIDE + kc + 8];
                uint2 up3 = *(const uint2*)&Pu[(wq2 * 16 + g + 8) * SSTRIDE + kc + 8];
                uint32_t Ah0 = MAIN2(up0.x, up0.y), Al0 = RESID2(up0.x, up0.y);
                uint32_t Ah1 = MAIN2(up1.x, up1.y), Al1 = RESID2(up1.x, up1.y);
                uint32_t Ah2 = MAIN2(up2.x, up2.y), Al2 = RESID2(up2.x, up2.y);
                uint32_t Ah3 = MAIN2(up3.x, up3.y), Al3 = RESID2(up3.x, up3.y);
                #pragma unroll
                for (int nf = 0; nf < 8; nf++) {
                    const int n0 = wd * 64 + nf * 8 + g;
                    uint32_t v0 = Vb[(kc    ) * QSTRIDE + n0];
                    uint32_t v1 = Vb[(kc + 1) * QSTRIDE + n0];
                    uint32_t v2 = Vb[(kc + 8) * QSTRIDE + n0];
                    uint32_t v3 = Vb[(kc + 9) * QSTRIDE + n0];
                    uint32_t Bh0 = MAIN2(v0, v1), Bl0 = RESID2(v0, v1);
                    uint32_t Bh1 = MAIN2(v2, v3), Bl1 = RESID2(v2, v3);
                    mma_bf16(oc[nf], Ah0, Ah1, Ah2, Ah3, Bl0, Bl1);
                    mma_bf16(oc[nf], Al0, Al1, Al2, Al3, Bh0, Bh1);
                    mma_bf16(oc[nf], Ah0, Ah1, Ah2, Ah3, Bh0, Bh1);
                }
            }
        }
        __syncthreads();
    }

    // ---------------- finalize: O / l, pack, store ----------------
    {
        const int wq2 = wid >> 2, wd = wid & 3;
        const float inv_lo = 1.f / lS[wq2 * 16 + g];
        const float inv_hi = 1.f / lS[wq2 * 16 + g + 8];
        const int r_lo = q0 + wq2 * 16 + g;
        const int r_hi = r_lo + 8;
        #pragma unroll
        for (int nf = 0; nf < 8; nf++) {
            const int n = h * D_ + wd * 64 + nf * 8 + 2 * tig;
            uint2 w0, w1;
            w0.x = pack_split(oc[nf][0] * inv_lo);
            w0.y = pack_split(oc[nf][1] * inv_lo);
            w1.x = pack_split(oc[nf][2] * inv_hi);
            w1.y = pack_split(oc[nf][3] * inv_hi);
            *(uint2*)&g_attn32[(size_t)r_lo * HID_ + n] = w0;
            *(uint2*)&g_attn32[(size_t)r_hi * HID_ + n] = w1;
        }
    }
}

// ---------------------------------------------------------------------------
// Launch
// ---------------------------------------------------------------------------
extern "C" void kernel_launch(void* const* d_in, const int* in_sizes, int n_in,
                              void* d_out, int out_size)
{
    const float* hidden    = (const float*)d_in[0];
    const int*   positions = (const int*)  d_in[1];
    const float* w_qkv     = (const float*)d_in[2];
    const float* w_o       = (const float*)d_in[3];
    const float* q_norm_w  = (const float*)d_in[4];
    const float* k_norm_w  = (const float*)d_in[5];
    float* out = (float*)d_out;

    float    *qkv_ptr = nullptr;
    uint32_t *hid32 = nullptr, *wqkv32 = nullptr, *wo32 = nullptr, *attn32 = nullptr;
    cudaGetSymbolAddress((void**)&qkv_ptr, g_qkv);
    cudaGetSymbolAddress((void**)&hid32,   g_hid32);
    cudaGetSymbolAddress((void**)&wqkv32,  g_wqkv32);
    cudaGetSymbolAddress((void**)&wo32,    g_wo32);
    cudaGetSymbolAddress((void**)&attn32,  g_attn32);

    cudaFuncSetAttribute(attn_kernel, cudaFuncAttributeMaxDynamicSharedMemorySize,
                         ATTN_SMEM_BYTES);

    // Pre-split all GEMM operands into packed bf16 hi/lo
    split_pack_kernel<<<1024, 256>>>(hidden, hid32,  (T_ * HID_) / 4);
    split_pack_kernel<<<2048, 256>>>(w_qkv,  wqkv32, (HID_ * QKV_N_) / 4);
    split_pack_kernel<<<1024, 256>>>(w_o,    wo32,   (HID_ * HID_) / 4);
    rope_table_kernel<<<T_, 128>>>(positions);

    // 1) QKV projection
    gemm_bf16s<<<dim3(QKV_N_ / 128, T_ / 128), 256>>>(hid32, wqkv32, qkv_ptr,
                                                      T_, QKV_N_, HID_);
    // 2) RMSNorm + RoPE (emits packed q/k/v)
    norm_rope_kernel<<<dim3(T_, NH_), 128>>>(q_norm_w, k_norm_w);

    // 3) Flash attention (emits packed attn output)
    attn_kernel<<<dim3(T_ / 32, NH_), 256, ATTN_SMEM_BYTES>>>();

    // 4) Output projection
    gemm_bf16s<<<dim3(HID_ / 128, T_ / 128), 256>>>(attn32, wo32, out,
                                                    T_, HID_, HID_);
}